// round 2
// baseline (speedup 1.0000x reference)
#include <cuda_runtime.h>
#include <cstdint>

#define KK 49          // kernel taps
#define CC 32          // out channels
#define WPB 256        // windows per block
#define XS 258         // x smem row stride in floats (even: LDS.64 aligned; (2k+win)%32 bank spread)
#define W_OFF 12644    // weight tile float offset: XS*KK=12642 rounded up to mult of 4 -> 16B aligned
#define NTHREADS 256

__device__ __forceinline__ void fma2(uint64_t& d, uint64_t a, uint64_t b) {
    asm("fma.rn.f32x2 %0, %1, %2, %0;" : "+l"(d) : "l"(a), "l"(b));
}
__device__ __forceinline__ uint64_t dup2(float w) {
    uint64_t r; uint32_t wb = __float_as_uint(w);
    asm("mov.b64 %0, {%1, %1};" : "=l"(r) : "r"(wb));
    return r;
}

extern __shared__ float smem[];   // [0, XS*KK) x tile (transposed), [W_OFF, W_OFF+KK*CC) weights [k][c]

__global__ void __launch_bounds__(NTHREADS, 2)
conv_im2col_kernel(const float* __restrict__ enc_x,
                   const float* __restrict__ weight,
                   const float* __restrict__ bias,
                   float* __restrict__ out, int W)
{
    float* x_s = smem;             // x_s[k*XS + win], win in [0,256)
    float* w_s = smem + W_OFF;     // w_s[k*32 + c], 16B-aligned base, 128B-aligned rows

    const int tid = threadIdx.x;

    // ---- stage weights transposed: [k][c] for LDS.128 broadcast ----
    for (int idx = tid; idx < KK * CC; idx += NTHREADS) {
        int k = idx >> 5;          // idx / 32
        int c = idx & 31;
        w_s[idx] = weight[c * KK + k];
    }

    // ---- stage enc_x tile: coalesced scalar loads, transposed smem store ----
    // tile = 256 windows * 49 taps = 12544 floats = exactly 49 per thread
    const float* xg = enc_x + (size_t)blockIdx.x * (WPB * KK);
    #pragma unroll 7
    for (int it = 0; it < KK; it++) {
        int e = tid + NTHREADS * it;
        float v = xg[e];
        int win = e / KK;
        int k   = e - win * KK;
        x_s[k * XS + win] = v;
    }
    __syncthreads();

    // ---- compute: thread = 8 channels x 4 windows (2 f32x2 accumulator pairs) ----
    const int lane64 = tid & 63;        // window-pair slot within block
    const int cgrp   = tid >> 6;        // 0..3 -> channels cgrp*8 .. +7 (warp-uniform)

    uint64_t acc[8][2];
    #pragma unroll
    for (int c = 0; c < 8; c++) { acc[c][0] = 0ull; acc[c][1] = 0ull; }

    #pragma unroll 7
    for (int k = 0; k < KK; k++) {
        const float* xr = &x_s[k * XS + 2 * lane64];
        uint64_t x0 = *(const uint64_t*)(xr);         // windows 2*lane64, +1
        uint64_t x1 = *(const uint64_t*)(xr + 128);   // windows +128, +129
        float4 wa = *(const float4*)&w_s[k * CC + cgrp * 8];      // 16B aligned
        float4 wb = *(const float4*)&w_s[k * CC + cgrp * 8 + 4];  // 16B aligned
        uint64_t wd;
        wd = dup2(wa.x); fma2(acc[0][0], x0, wd); fma2(acc[0][1], x1, wd);
        wd = dup2(wa.y); fma2(acc[1][0], x0, wd); fma2(acc[1][1], x1, wd);
        wd = dup2(wa.z); fma2(acc[2][0], x0, wd); fma2(acc[2][1], x1, wd);
        wd = dup2(wa.w); fma2(acc[3][0], x0, wd); fma2(acc[3][1], x1, wd);
        wd = dup2(wb.x); fma2(acc[4][0], x0, wd); fma2(acc[4][1], x1, wd);
        wd = dup2(wb.y); fma2(acc[5][0], x0, wd); fma2(acc[5][1], x1, wd);
        wd = dup2(wb.z); fma2(acc[6][0], x0, wd); fma2(acc[6][1], x1, wd);
        wd = dup2(wb.w); fma2(acc[7][0], x0, wd); fma2(acc[7][1], x1, wd);
    }

    // ---- epilogue: + bias, coalesced STG.64 ----
    const size_t winbase = (size_t)blockIdx.x * WPB + 2 * lane64;
    #pragma unroll
    for (int c = 0; c < 8; c++) {
        float b = __ldg(&bias[cgrp * 8 + c]);
        #pragma unroll
        for (int j = 0; j < 2; j++) {
            float2 r;
            r.x = __uint_as_float((uint32_t)(acc[c][j]       )) + b;
            r.y = __uint_as_float((uint32_t)(acc[c][j] >> 32)) + b;
            *(float2*)&out[(size_t)(cgrp * 8 + c) * W + winbase + 128 * j] = r;
        }
    }
}

extern "C" void kernel_launch(void* const* d_in, const int* in_sizes, int n_in,
                              void* d_out, int out_size)
{
    const float* enc_x  = (const float*)d_in[0];
    const float* weight = (const float*)d_in[1];
    const float* bias   = (const float*)d_in[2];
    float* out = (float*)d_out;

    int W = in_sizes[0] / KK;              // 1048576
    int blocks = W / WPB;                  // 4096

    int smem_bytes = (W_OFF + KK * CC) * (int)sizeof(float);     // 56848 B
    cudaFuncSetAttribute(conv_im2col_kernel,
                         cudaFuncAttributeMaxDynamicSharedMemorySize, smem_bytes);
    conv_im2col_kernel<<<blocks, NTHREADS, smem_bytes>>>(enc_x, weight, bias, out, W);
}

// round 3
// speedup vs baseline: 1.3803x; 1.3803x over previous
#include <cuda_runtime.h>
#include <cstdint>

#define KK 49
#define CC 32
#define WPB 128
#define NT  256

__device__ __forceinline__ void fma2(uint64_t& d, uint64_t a, uint64_t b) {
    asm("fma.rn.f32x2 %0, %1, %2, %0;" : "+l"(d) : "l"(a), "l"(b));
}
__device__ __forceinline__ uint64_t dup2(float w) {
    uint64_t r; uint32_t wb = __float_as_uint(w);
    asm("mov.b64 %0, {%1, %1};" : "=l"(r) : "r"(wb));
    return r;
}
__device__ __forceinline__ uint64_t pack2(float a, float b) {
    uint64_t r;
    asm("mov.b64 %0, {%1, %2};" : "=l"(r)
        : "r"(__float_as_uint(a)), "r"(__float_as_uint(b)));
    return r;
}
__device__ __forceinline__ void cp16(void* dst_smem, const void* src) {
    uint32_t d = (uint32_t)__cvta_generic_to_shared(dst_smem);
    asm volatile("cp.async.cg.shared.global [%0], [%1], 16;" :: "r"(d), "l"(src));
}

__global__ void __launch_bounds__(NT, 4)
conv_im2col_kernel(const float* __restrict__ enc_x,
                   const float* __restrict__ weight,
                   const float* __restrict__ bias,
                   float* __restrict__ out, int W)
{
    __shared__ __align__(16) float x_s[WPB * KK];   // verbatim gmem layout [win][k]
    __shared__ __align__(16) float w_s[KK * CC];    // transposed [k][c]

    const int tid = threadIdx.x;

    // ---- stage x tile: 1568 x 16B cp.async, zero register traffic ----
    const float4* xg = (const float4*)(enc_x + (size_t)blockIdx.x * (WPB * KK));
    #pragma unroll
    for (int i = 0; i < 7; i++) {                   // 7*256 = 1792 slots, 1568 used
        int e = tid + NT * i;
        if (e < WPB * KK / 4) cp16(&((float4*)x_s)[e], &xg[e]);
    }
    asm volatile("cp.async.commit_group;" ::: "memory");

    // ---- stage weights transposed [k][c] (tiny; L2-resident after first wave) ----
    #pragma unroll
    for (int i = tid; i < KK * CC; i += NT) {
        int k = i >> 5, c = i & 31;
        w_s[i] = weight[c * KK + k];
    }
    asm volatile("cp.async.wait_group 0;" ::: "memory");
    __syncthreads();

    // ---- compute: warp -> 4 channels; lane -> windows {l, l+32, l+64, l+96} ----
    const int lane = tid & 31;
    const int wid  = tid >> 5;                      // 0..7 -> channels wid*4..+3
    const float* xp = x_s + lane * KK;              // stride 49 (odd) -> conflict-free LDS

    uint64_t acc[4][2];
    #pragma unroll
    for (int c = 0; c < 4; c++) { acc[c][0] = 0ull; acc[c][1] = 0ull; }

    #pragma unroll 7
    for (int k = 0; k < KK; k++) {
        uint64_t x0 = pack2(xp[k],           xp[k + 32 * KK]);   // wins l, l+32
        uint64_t x1 = pack2(xp[k + 64 * KK], xp[k + 96 * KK]);   // wins l+64, l+96
        float4 wv = *(const float4*)&w_s[k * CC + wid * 4];      // broadcast LDS.128
        uint64_t wd;
        wd = dup2(wv.x); fma2(acc[0][0], x0, wd); fma2(acc[0][1], x1, wd);
        wd = dup2(wv.y); fma2(acc[1][0], x0, wd); fma2(acc[1][1], x1, wd);
        wd = dup2(wv.z); fma2(acc[2][0], x0, wd); fma2(acc[2][1], x1, wd);
        wd = dup2(wv.w); fma2(acc[3][0], x0, wd); fma2(acc[3][1], x1, wd);
    }

    // ---- epilogue: + bias, coalesced STG.32 (consecutive lanes -> consecutive addrs) ----
    const size_t bb = (size_t)blockIdx.x * WPB;
    #pragma unroll
    for (int c = 0; c < 4; c++) {
        float b = __ldg(&bias[wid * 4 + c]);
        float* op = out + (size_t)(wid * 4 + c) * W + bb + lane;
        op[ 0] = __uint_as_float((uint32_t)(acc[c][0]      )) + b;
        op[32] = __uint_as_float((uint32_t)(acc[c][0] >> 32)) + b;
        op[64] = __uint_as_float((uint32_t)(acc[c][1]      )) + b;
        op[96] = __uint_as_float((uint32_t)(acc[c][1] >> 32)) + b;
    }
}

extern "C" void kernel_launch(void* const* d_in, const int* in_sizes, int n_in,
                              void* d_out, int out_size)
{
    const float* enc_x  = (const float*)d_in[0];
    const float* weight = (const float*)d_in[1];
    const float* bias   = (const float*)d_in[2];
    float* out = (float*)d_out;

    int W = in_sizes[0] / KK;        // 1048576
    int blocks = W / WPB;            // 8192

    conv_im2col_kernel<<<blocks, NT>>>(enc_x, weight, bias, out, W);
}